// round 2
// baseline (speedup 1.0000x reference)
#include <cuda_runtime.h>
#include <math.h>

// Problem dims
#define NROWS 8192
#define DDIM  1024

// Tiling
#define BM 128
#define BN 128
#define BK 32
#define TM 8
#define TN 8
#define NTHREADS 256   // 16x16 thread grid

// Scratch (allocation-free rule: __device__ globals)
__device__ float g_h[(size_t)NROWS * DDIM];          // 32 MB
__device__ float g_P[(size_t)NROWS * NROWS];         // 256 MB
__device__ float g_rowsum[NROWS];

// ---------------------------------------------------------------------------
// Shared GEMM mainloop. A is always K-major (row-major, K contiguous).
// B_KMAJOR=true  : B stored [n, k] K-contiguous (NT gemm, C = A * B^T)
// B_KMAJOR=false : B stored [k, n] N-contiguous (NN gemm, C = A * B)
// As/Bs are transposed to [BK][128] for conflict-light float4 compute reads.
// ---------------------------------------------------------------------------
template <bool B_KMAJOR>
__device__ __forceinline__ void gemm_mainloop(
    const float* __restrict__ Ag, size_t lda,
    const float* __restrict__ Bg, size_t ldb,
    int K, float acc[TM][TN],
    float (*As)[BM], float (*Bs)[BN],
    int tid, int tx, int ty)
{
    for (int k0 = 0; k0 < K; k0 += BK) {
        // Load A tile [BM rows x BK k] -> As[k][m] (transposed scatter)
        #pragma unroll
        for (int i = 0; i < 4; i++) {
            int f   = tid + i * NTHREADS;      // 0..1023
            int row = f >> 3;                  // 0..127
            int k4  = (f & 7) << 2;            // 0,4,...,28
            float4 v = *(const float4*)(Ag + (size_t)row * lda + k0 + k4);
            As[k4 + 0][row] = v.x;
            As[k4 + 1][row] = v.y;
            As[k4 + 2][row] = v.z;
            As[k4 + 3][row] = v.w;
        }
        if (B_KMAJOR) {
            #pragma unroll
            for (int i = 0; i < 4; i++) {
                int f   = tid + i * NTHREADS;
                int row = f >> 3;
                int k4  = (f & 7) << 2;
                float4 v = *(const float4*)(Bg + (size_t)row * ldb + k0 + k4);
                Bs[k4 + 0][row] = v.x;
                Bs[k4 + 1][row] = v.y;
                Bs[k4 + 2][row] = v.z;
                Bs[k4 + 3][row] = v.w;
            }
        } else {
            #pragma unroll
            for (int i = 0; i < 4; i++) {
                int f    = tid + i * NTHREADS;
                int krow = f >> 5;             // 0..31
                int n4   = (f & 31) << 2;      // 0..124
                float4 v = *(const float4*)(Bg + (size_t)(k0 + krow) * ldb + n4);
                *(float4*)&Bs[krow][n4] = v;
            }
        }
        __syncthreads();

        #pragma unroll
        for (int k = 0; k < BK; k++) {
            float ra[TM], rb[TN];
            *(float4*)&ra[0] = *(const float4*)&As[k][ty * TM];
            *(float4*)&ra[4] = *(const float4*)&As[k][ty * TM + 4];
            *(float4*)&rb[0] = *(const float4*)&Bs[k][tx * TN];
            *(float4*)&rb[4] = *(const float4*)&Bs[k][tx * TN + 4];
            #pragma unroll
            for (int i = 0; i < TM; i++)
                #pragma unroll
                for (int j = 0; j < TN; j++)
                    acc[i][j] = fmaf(ra[i], rb[j], acc[i][j]);
        }
        __syncthreads();
    }
}

// ---------------------------------------------------------------------------
// K1: h = x @ W^T + b     (NT gemm: both x and W are K-contiguous)
// ---------------------------------------------------------------------------
__global__ __launch_bounds__(NTHREADS)
void k1_linear(const float* __restrict__ X, const float* __restrict__ W,
               const float* __restrict__ bias)
{
    __shared__ float As[BK][BM];
    __shared__ float Bs[BK][BN];
    int tid = threadIdx.x;
    int tx = tid & 15, ty = tid >> 4;
    int bx = blockIdx.x, by = blockIdx.y;

    const float* Ag = X + (size_t)by * BM * DDIM;
    const float* Bg = W + (size_t)bx * BN * DDIM;

    float acc[TM][TN] = {};
    gemm_mainloop<true>(Ag, DDIM, Bg, DDIM, DDIM, acc, As, Bs, tid, tx, ty);

    int r0 = by * BM + ty * TM;
    int c0 = bx * BN + tx * TN;
    float bb[TN];
    *(float4*)&bb[0] = *(const float4*)&bias[c0];
    *(float4*)&bb[4] = *(const float4*)&bias[c0 + 4];

    #pragma unroll
    for (int i = 0; i < TM; i++) {
        float4 v0 = make_float4(acc[i][0] + bb[0], acc[i][1] + bb[1],
                                acc[i][2] + bb[2], acc[i][3] + bb[3]);
        float4 v1 = make_float4(acc[i][4] + bb[4], acc[i][5] + bb[5],
                                acc[i][6] + bb[6], acc[i][7] + bb[7]);
        float* dst = g_h + (size_t)(r0 + i) * DDIM + c0;
        *(float4*)dst       = v0;
        *(float4*)(dst + 4) = v1;
    }
}

// ---------------------------------------------------------------------------
// zero rowsum accumulator (re-run every replay)
// ---------------------------------------------------------------------------
__global__ void k_zero_rowsum()
{
    int i = blockIdx.x * blockDim.x + threadIdx.x;
    if (i < NROWS) g_rowsum[i] = 0.0f;
}

// ---------------------------------------------------------------------------
// K2: P = exp(tanh(h @ h^T)), symmetric (only upper-tri block grid computed),
//     with row-sum accumulation. No softmax max needed: tanh <= 1 bounds exp.
// ---------------------------------------------------------------------------
__global__ __launch_bounds__(NTHREADS)
void k2_scores()
{
    int bx = blockIdx.x;   // column block
    int by = blockIdx.y;   // row block
    if (by > bx) return;   // symmetry: compute upper triangle only

    __shared__ float As[BK][BM];
    __shared__ float Bs[BK][BN];
    __shared__ float scol[BN];

    int tid = threadIdx.x;
    int tx = tid & 15, ty = tid >> 4;
    if (tid < BN) scol[tid] = 0.0f;   // synced by first __syncthreads in mainloop

    const float* Ag = g_h + (size_t)by * BM * DDIM;
    const float* Bg = g_h + (size_t)bx * BN * DDIM;

    float acc[TM][TN] = {};
    gemm_mainloop<true>(Ag, DDIM, Bg, DDIM, DDIM, acc, As, Bs, tid, tx, ty);

    int r0 = by * BM + ty * TM;
    int c0 = bx * BN + tx * TN;

    float p[TM][TN];
    float rsum[TM] = {};
    float csum[TN] = {};
    #pragma unroll
    for (int i = 0; i < TM; i++)
        #pragma unroll
        for (int j = 0; j < TN; j++) {
            float v = __expf(tanhf(acc[i][j]));
            p[i][j] = v;
            rsum[i] += v;
            csum[j] += v;
        }

    // direct store (coalesced float4)
    #pragma unroll
    for (int i = 0; i < TM; i++) {
        float* dst = g_P + (size_t)(r0 + i) * NROWS + c0;
        *(float4*)dst       = make_float4(p[i][0], p[i][1], p[i][2], p[i][3]);
        *(float4*)(dst + 4) = make_float4(p[i][4], p[i][5], p[i][6], p[i][7]);
    }
    // mirror store for the symmetric block (scattered; accepted this round)
    if (bx != by) {
        #pragma unroll
        for (int j = 0; j < TN; j++) {
            float* dst = g_P + (size_t)(c0 + j) * NROWS + r0;
            #pragma unroll
            for (int i = 0; i < TM; i++) dst[i] = p[i][j];
        }
    }

    // row sums: reduce across the 16 tx lanes (contiguous within a warp)
    #pragma unroll
    for (int i = 0; i < TM; i++) {
        float v = rsum[i];
        v += __shfl_down_sync(0xffffffffu, v, 8, 16);
        v += __shfl_down_sync(0xffffffffu, v, 4, 16);
        v += __shfl_down_sync(0xffffffffu, v, 2, 16);
        v += __shfl_down_sync(0xffffffffu, v, 1, 16);
        if (tx == 0) atomicAdd(&g_rowsum[r0 + i], v);
    }

    // column sums feed the mirrored rows' rowsum (off-diagonal blocks only)
    if (bx != by) {
        #pragma unroll
        for (int j = 0; j < TN; j++)
            atomicAdd(&scol[tx * TN + j], csum[j]);
        __syncthreads();
        if (tid < BN) atomicAdd(&g_rowsum[bx * BN + tid], scol[tid]);
    }
}

// ---------------------------------------------------------------------------
// K3: out = tanh( (P @ h) / rowsum )   (NN gemm: P K-contig, h N-contig)
// ---------------------------------------------------------------------------
__global__ __launch_bounds__(NTHREADS)
void k3_out(float* __restrict__ out)
{
    __shared__ float As[BK][BM];
    __shared__ float Bs[BK][BN];
    int tid = threadIdx.x;
    int tx = tid & 15, ty = tid >> 4;
    int bx = blockIdx.x, by = blockIdx.y;

    const float* Ag = g_P + (size_t)by * BM * NROWS;
    const float* Bg = g_h + (size_t)bx * BN;   // (k=0, col block) base

    float acc[TM][TN] = {};
    gemm_mainloop<false>(Ag, NROWS, Bg, DDIM, NROWS, acc, As, Bs, tid, tx, ty);

    int r0 = by * BM + ty * TM;
    int c0 = bx * BN + tx * TN;
    #pragma unroll
    for (int i = 0; i < TM; i++) {
        float inv = 1.0f / g_rowsum[r0 + i];
        float4 v0 = make_float4(tanhf(acc[i][0] * inv), tanhf(acc[i][1] * inv),
                                tanhf(acc[i][2] * inv), tanhf(acc[i][3] * inv));
        float4 v1 = make_float4(tanhf(acc[i][4] * inv), tanhf(acc[i][5] * inv),
                                tanhf(acc[i][6] * inv), tanhf(acc[i][7] * inv));
        float* dst = out + (size_t)(r0 + i) * DDIM + c0;
        *(float4*)dst       = v0;
        *(float4*)(dst + 4) = v1;
    }
}

// ---------------------------------------------------------------------------
extern "C" void kernel_launch(void* const* d_in, const int* in_sizes, int n_in,
                              void* d_out, int out_size)
{
    const float* x = (const float*)d_in[0];   // [8192, 1024]
    const float* W = (const float*)d_in[1];   // [1024, 1024]
    const float* b = (const float*)d_in[2];   // [1024]
    float* out = (float*)d_out;               // [8192, 1024]

    dim3 t(NTHREADS);
    k1_linear<<<dim3(DDIM / BN, NROWS / BM), t>>>(x, W, b);
    k_zero_rowsum<<<NROWS / 256, 256>>>();
    k2_scores<<<dim3(NROWS / BN, NROWS / BM), t>>>();
    k3_out<<<dim3(DDIM / BN, NROWS / BM), t>>>(out);
}

// round 4
// speedup vs baseline: 5.6177x; 5.6177x over previous
#include <cuda_runtime.h>
#include <cuda_fp16.h>
#include <cstdint>
#include <math.h>

#define NR 8192
#define ND 1024
#define BM 128
#define BN 128
#define BKD 32
#define NTHR 256

// smem tile offsets within a stage (each tile 128x32 fp16 = 8192 B)
#define T_AHI 0
#define T_ALO 8192
#define T_BHI 16384
#define T_BLO 24576

// scratch
__device__ __half g_xh[(size_t)NR * ND], g_xl[(size_t)NR * ND];
__device__ __half g_Wh[(size_t)ND * ND], g_Wl[(size_t)ND * ND];
__device__ __half g_hh[(size_t)NR * ND], g_hl[(size_t)NR * ND];
__device__ __half g_hT[(size_t)ND * NR];
__device__ __half g_Pf[(size_t)NR * NR];
__device__ float g_rowsum[NR];

// ------------------------------------------------------------------ helpers
__device__ __forceinline__ uint32_t smem_u32(const void* p) {
    uint32_t a;
    asm("{ .reg .u64 t; cvta.to.shared.u64 t, %1; cvt.u32.u64 %0, t; }" : "=r"(a) : "l"(p));
    return a;
}
__device__ __forceinline__ void cp16(uint32_t s, const __half* g) {
    asm volatile("cp.async.cg.shared.global [%0], [%1], 16;"
                 :: "r"(s), "l"(__cvta_generic_to_global((const void*)g)) : "memory");
}
__device__ __forceinline__ void cp_commit() {
    asm volatile("cp.async.commit_group;" ::: "memory");
}
template <int N> __device__ __forceinline__ void cp_wait() {
    asm volatile("cp.async.wait_group %0;" :: "n"(N) : "memory");
}
__device__ __forceinline__ void ldsm4(uint32_t* r, uint32_t a) {
    asm volatile("ldmatrix.sync.aligned.m8n8.x4.shared.b16 {%0,%1,%2,%3}, [%4];"
                 : "=r"(r[0]), "=r"(r[1]), "=r"(r[2]), "=r"(r[3]) : "r"(a));
}
__device__ __forceinline__ void mma16816(float* c, const uint32_t* a, uint32_t b0, uint32_t b1) {
    asm volatile(
        "mma.sync.aligned.m16n8k16.row.col.f32.f16.f16.f32 "
        "{%0,%1,%2,%3},{%4,%5,%6,%7},{%8,%9},{%0,%1,%2,%3};"
        : "+f"(c[0]), "+f"(c[1]), "+f"(c[2]), "+f"(c[3])
        : "r"(a[0]), "r"(a[1]), "r"(a[2]), "r"(a[3]), "r"(b0), "r"(b1));
}
__device__ __forceinline__ float ftanh(float x) {
    float y; asm("tanh.approx.f32 %0, %1;" : "=f"(y) : "f"(x)); return y;
}
__device__ __forceinline__ void split16(float v, __half& h, __half& l) {
    h = __float2half_rn(v);
    l = __float2half_rn(v - __half2float(h));
}
// swizzled smem byte offset for (row, 16B-chunk) within a [128][32] fp16 tile
__device__ __forceinline__ uint32_t swz(int row, int c) {
    return (uint32_t)(row * 64 + ((c ^ ((row >> 1) & 3)) << 4));
}

// load one [128][32] fp16 tile (2 x 16B chunks per thread)
__device__ __forceinline__ void load_tile(const __half* __restrict__ base, size_t ld,
                                          int k0, uint32_t st, int tid) {
    #pragma unroll
    for (int i = 0; i < 2; i++) {
        int idx = tid + i * NTHR;
        int row = idx >> 2, c = idx & 3;
        cp16(st + swz(row, c), base + (size_t)row * ld + k0 + c * 8);
    }
}

// ------------------------------------------------------- GEMM (0=K1,1=K2,2=K3)
template <int MODE>
__global__ __launch_bounds__(NTHR)
void gemm_tc(const float* __restrict__ bias, float* __restrict__ out)
{
    constexpr int STAGE = (MODE < 2) ? 32768 : 16384;
    constexpr int K = (MODE == 2) ? NR : ND;
    constexpr int NC = K / BKD;

    extern __shared__ char smem[];
    const uint32_t sb = smem_u32(smem);
    const int tid = threadIdx.x, lane = tid & 31, wid = tid >> 5;
    const int bx = blockIdx.x, by = blockIdx.y;
    const int mo = (wid & 3) * 32, no = (wid >> 2) * 64;

    const __half *Ahi, *Alo, *Bhi, *Blo;
    size_t lda, ldb;
    if (MODE == 0) {
        Ahi = g_xh + (size_t)by * BM * ND; Alo = g_xl + (size_t)by * BM * ND;
        Bhi = g_Wh + (size_t)bx * BN * ND; Blo = g_Wl + (size_t)bx * BN * ND;
        lda = ND; ldb = ND;
    } else if (MODE == 1) {
        Ahi = g_hh + (size_t)by * BM * ND; Alo = g_hl + (size_t)by * BM * ND;
        Bhi = g_hh + (size_t)bx * BN * ND; Blo = g_hl + (size_t)bx * BN * ND;
        lda = ND; ldb = ND;
    } else {
        Ahi = g_Pf + (size_t)by * BM * NR; Alo = nullptr;
        Bhi = g_hT + (size_t)bx * BN * NR; Blo = nullptr;
        lda = NR; ldb = NR;
    }

    float c[2][8][4] = {};

    // prologue: stage 0
    {
        uint32_t st = sb;
        if (MODE < 2) {
            load_tile(Ahi, lda, 0, st + T_AHI, tid);
            load_tile(Alo, lda, 0, st + T_ALO, tid);
            load_tile(Bhi, ldb, 0, st + T_BHI, tid);
            load_tile(Blo, ldb, 0, st + T_BLO, tid);
        } else {
            load_tile(Ahi, lda, 0, st + 0, tid);
            load_tile(Bhi, ldb, 0, st + 8192, tid);
        }
        cp_commit();
    }

    for (int i = 0; i < NC; i++) {
        const int s = i & 1;
        if (i + 1 < NC) {
            uint32_t st = sb + (s ^ 1) * STAGE;
            int k0 = (i + 1) * BKD;
            if (MODE < 2) {
                load_tile(Ahi, lda, k0, st + T_AHI, tid);
                load_tile(Alo, lda, k0, st + T_ALO, tid);
                load_tile(Bhi, ldb, k0, st + T_BHI, tid);
                load_tile(Blo, ldb, k0, st + T_BLO, tid);
            } else {
                load_tile(Ahi, lda, k0, st + 0, tid);
                load_tile(Bhi, ldb, k0, st + 8192, tid);
            }
            cp_commit();
            cp_wait<1>();
        } else {
            cp_wait<0>();
        }
        __syncthreads();

        const uint32_t st = sb + s * STAGE;
        const int NP = (MODE < 2) ? 3 : 1;
        #pragma unroll
        for (int p = 0; p < NP; p++) {
            uint32_t aoff, boff;
            if (MODE < 2) {
                aoff = st + ((p == 1) ? T_ALO : T_AHI);
                boff = st + ((p == 2) ? T_BLO : T_BHI);
            } else { aoff = st; boff = st + 8192; }
            #pragma unroll
            for (int ks = 0; ks < 2; ks++) {
                uint32_t a[2][4];
                #pragma unroll
                for (int mf = 0; mf < 2; mf++) {
                    int row = mo + mf * 16 + (lane & 15);
                    int ch = 2 * ks + (lane >> 4);
                    ldsm4(a[mf], aoff + swz(row, ch));
                }
                uint32_t b[4][4];
                #pragma unroll
                for (int np = 0; np < 4; np++) {
                    int row = no + np * 16 + (lane & 7) + ((lane >> 4) << 3);
                    int ch = 2 * ks + ((lane >> 3) & 1);
                    ldsm4(b[np], boff + swz(row, ch));
                }
                #pragma unroll
                for (int mf = 0; mf < 2; mf++)
                    #pragma unroll
                    for (int nf = 0; nf < 8; nf++)
                        mma16816(c[mf][nf], a[mf],
                                 b[nf >> 1][(nf & 1) * 2], b[nf >> 1][(nf & 1) * 2 + 1]);
            }
        }
        __syncthreads();
    }

    // --------------------------------------------------------- epilogue
    float rs[2][2] = {};   // MODE 1 row sums: [mfrag][half]
    #pragma unroll
    for (int mf = 0; mf < 2; mf++) {
        const int r0 = by * BM + mo + mf * 16 + (lane >> 2);
        const int r1 = r0 + 8;
        float inv0 = 0.f, inv1 = 0.f;
        if (MODE == 2) {
            inv0 = 1.0f / __ldg(&g_rowsum[r0]);
            inv1 = 1.0f / __ldg(&g_rowsum[r1]);
        }
        #pragma unroll
        for (int nf = 0; nf < 8; nf++) {
            const int col = bx * BN + no + nf * 8 + 2 * (lane & 3);
            float v0 = c[mf][nf][0], v1 = c[mf][nf][1];
            float v2 = c[mf][nf][2], v3 = c[mf][nf][3];
            if (MODE == 0) {
                float b0 = __ldg(&bias[col]), b1 = __ldg(&bias[col + 1]);
                v0 += b0; v1 += b1; v2 += b0; v3 += b1;
                __half h0, l0, h1, l1, h2, l2, h3, l3;
                split16(v0, h0, l0); split16(v1, h1, l1);
                split16(v2, h2, l2); split16(v3, h3, l3);
                *(__half2*)(g_hh + (size_t)r0 * ND + col) = __halves2half2(h0, h1);
                *(__half2*)(g_hl + (size_t)r0 * ND + col) = __halves2half2(l0, l1);
                *(__half2*)(g_hh + (size_t)r1 * ND + col) = __halves2half2(h2, h3);
                *(__half2*)(g_hl + (size_t)r1 * ND + col) = __halves2half2(l2, l3);
                g_hT[(size_t)col * NR + r0] = h0; g_hT[(size_t)(col + 1) * NR + r0] = h1;
                g_hT[(size_t)col * NR + r1] = h2; g_hT[(size_t)(col + 1) * NR + r1] = h3;
            } else if (MODE == 1) {
                float p0 = __expf(ftanh(v0)), p1 = __expf(ftanh(v1));
                float p2 = __expf(ftanh(v2)), p3 = __expf(ftanh(v3));
                rs[mf][0] += p0 + p1; rs[mf][1] += p2 + p3;
                *(__half2*)(g_Pf + (size_t)r0 * NR + col) =
                    __halves2half2(__float2half_rn(p0), __float2half_rn(p1));
                *(__half2*)(g_Pf + (size_t)r1 * NR + col) =
                    __halves2half2(__float2half_rn(p2), __float2half_rn(p3));
            } else {
                float2 o0 = make_float2(tanhf(v0 * inv0), tanhf(v1 * inv0));
                float2 o1 = make_float2(tanhf(v2 * inv1), tanhf(v3 * inv1));
                *(float2*)(out + (size_t)r0 * ND + col) = o0;
                *(float2*)(out + (size_t)r1 * ND + col) = o1;
            }
        }
    }
    if (MODE == 1) {
        #pragma unroll
        for (int mf = 0; mf < 2; mf++)
            #pragma unroll
            for (int hh = 0; hh < 2; hh++) {
                float v = rs[mf][hh];
                v += __shfl_xor_sync(0xffffffffu, v, 1);
                v += __shfl_xor_sync(0xffffffffu, v, 2);
                if ((lane & 3) == 0) {
                    int r = by * BM + mo + mf * 16 + (lane >> 2) + hh * 8;
                    atomicAdd(&g_rowsum[r], v);
                }
            }
    }
}

// ------------------------------------------------------------- small kernels
__global__ void k_split(const float* __restrict__ src, __half* __restrict__ hi,
                        __half* __restrict__ lo, int n4)
{
    int i = blockIdx.x * blockDim.x + threadIdx.x;
    if (i >= n4) return;
    float4 v = ((const float4*)src)[i];
    __half h[4], l[4];
    split16(v.x, h[0], l[0]); split16(v.y, h[1], l[1]);
    split16(v.z, h[2], l[2]); split16(v.w, h[3], l[3]);
    ((uint2*)hi)[i] = *(uint2*)h;
    ((uint2*)lo)[i] = *(uint2*)l;
}
__global__ void k_zero_rowsum()
{
    int i = blockIdx.x * blockDim.x + threadIdx.x;
    if (i < NR) g_rowsum[i] = 0.0f;
}

// ------------------------------------------------------------------ launcher
extern "C" void kernel_launch(void* const* d_in, const int* in_sizes, int n_in,
                              void* d_out, int out_size)
{
    const float* x = (const float*)d_in[0];
    const float* W = (const float*)d_in[1];
    const float* b = (const float*)d_in[2];
    float* out = (float*)d_out;

    cudaFuncSetAttribute(gemm_tc<0>, cudaFuncAttributeMaxDynamicSharedMemorySize, 65536);
    cudaFuncSetAttribute(gemm_tc<1>, cudaFuncAttributeMaxDynamicSharedMemorySize, 65536);
    cudaFuncSetAttribute(gemm_tc<2>, cudaFuncAttributeMaxDynamicSharedMemorySize, 32768);

    __half *xh, *xl, *wh, *wl;
    cudaGetSymbolAddress((void**)&xh, g_xh); cudaGetSymbolAddress((void**)&xl, g_xl);
    cudaGetSymbolAddress((void**)&wh, g_Wh); cudaGetSymbolAddress((void**)&wl, g_Wl);

    int nx4 = NR * ND / 4, nw4 = ND * ND / 4;
    k_split<<<(nx4 + 255) / 256, 256>>>(x, xh, xl, nx4);
    k_split<<<(nw4 + 255) / 256, 256>>>(W, wh, wl, nw4);
    k_zero_rowsum<<<NR / 256, 256>>>();

    gemm_tc<0><<<dim3(ND / BN, NR / BM), NTHR, 65536>>>(b, nullptr);
    gemm_tc<1><<<dim3(NR / BN, NR / BM), NTHR, 65536>>>(nullptr, nullptr);
    gemm_tc<2><<<dim3(ND / BN, NR / BM), NTHR, 32768>>>(nullptr, out);
}

// round 6
// speedup vs baseline: 8.6503x; 1.5398x over previous
#include <cuda_runtime.h>
#include <cuda_fp16.h>
#include <cstdint>
#include <math.h>

#define NR 8192
#define ND 1024
#define BM 128
#define BN 128
#define BKD 32
#define NTHR 256

// smem tile offsets within a stage (each tile 128x32 fp16 = 8192 B)
#define T_AHI 0
#define T_ALO 8192
#define T_BHI 16384
#define T_BLO 24576

// scratch
__device__ __half g_xh[(size_t)NR * ND], g_xl[(size_t)NR * ND];
__device__ __half g_Wh[(size_t)ND * ND], g_Wl[(size_t)ND * ND];
__device__ __half g_hh[(size_t)NR * ND], g_hl[(size_t)NR * ND];
__device__ __half g_hT[(size_t)ND * NR];
__device__ __half g_Pf[(size_t)NR * NR];
__device__ float g_rowsum[NR];

// ------------------------------------------------------------------ helpers
__device__ __forceinline__ uint32_t smem_u32(const void* p) {
    uint32_t a;
    asm("{ .reg .u64 t; cvta.to.shared.u64 t, %1; cvt.u32.u64 %0, t; }" : "=r"(a) : "l"(p));
    return a;
}
__device__ __forceinline__ void cp16(uint32_t s, const __half* g) {
    asm volatile("cp.async.cg.shared.global [%0], [%1], 16;"
                 :: "r"(s), "l"(__cvta_generic_to_global((const void*)g)) : "memory");
}
__device__ __forceinline__ void cp_commit() {
    asm volatile("cp.async.commit_group;" ::: "memory");
}
template <int N> __device__ __forceinline__ void cp_wait() {
    asm volatile("cp.async.wait_group %0;" :: "n"(N) : "memory");
}
__device__ __forceinline__ void ldsm4(uint32_t* r, uint32_t a) {
    asm volatile("ldmatrix.sync.aligned.m8n8.x4.shared.b16 {%0,%1,%2,%3}, [%4];"
                 : "=r"(r[0]), "=r"(r[1]), "=r"(r[2]), "=r"(r[3]) : "r"(a));
}
__device__ __forceinline__ void mma16816(float* c, const uint32_t* a, uint32_t b0, uint32_t b1) {
    asm volatile(
        "mma.sync.aligned.m16n8k16.row.col.f32.f16.f16.f32 "
        "{%0,%1,%2,%3},{%4,%5,%6,%7},{%8,%9},{%0,%1,%2,%3};"
        : "+f"(c[0]), "+f"(c[1]), "+f"(c[2]), "+f"(c[3])
        : "r"(a[0]), "r"(a[1]), "r"(a[2]), "r"(a[3]), "r"(b0), "r"(b1));
}
__device__ __forceinline__ float ftanh(float x) {
    float y; asm("tanh.approx.f32 %0, %1;" : "=f"(y) : "f"(x)); return y;
}
__device__ __forceinline__ void split16(float v, __half& h, __half& l) {
    h = __float2half_rn(v);
    l = __float2half_rn(v - __half2float(h));
}
// swizzled smem byte offset for (row, 16B-chunk) within a [128][32] fp16 tile
__device__ __forceinline__ uint32_t swz(int row, int c) {
    return (uint32_t)(row * 64 + ((c ^ ((row >> 1) & 3)) << 4));
}

// load one [128][32] fp16 tile (2 x 16B chunks per thread)
__device__ __forceinline__ void load_tile(const __half* __restrict__ base, size_t ld,
                                          int k0, uint32_t st, int tid) {
    #pragma unroll
    for (int i = 0; i < 2; i++) {
        int idx = tid + i * NTHR;
        int row = idx >> 2, c = idx & 3;
        cp16(st + swz(row, c), base + (size_t)row * ld + k0 + c * 8);
    }
}

// ------------------------------------------------------- GEMM (0=K1,1=K2,2=K3)
// MODE 1 computes only by<=bx blocks; mirrors P and accumulates both row and
// column sums (tanh bounds scores, so exp needs no max subtraction).
template <int MODE>
__global__ __launch_bounds__(NTHR, 2)
void gemm_tc(const float* __restrict__ bias, float* __restrict__ out)
{
    constexpr int STAGE = (MODE < 2) ? 32768 : 16384;
    constexpr int K = (MODE == 2) ? NR : ND;
    constexpr int NC = K / BKD;

    extern __shared__ char smem[];
    const uint32_t sb = smem_u32(smem);
    const int tid = threadIdx.x, lane = tid & 31, wid = tid >> 5;
    const int bx = blockIdx.x, by = blockIdx.y;
    if (MODE == 1 && by > bx) return;   // symmetry (uniform whole-CTA exit)
    const int mo = (wid & 3) * 32, no = (wid >> 2) * 64;

    const __half *Ahi, *Alo, *Bhi, *Blo;
    size_t lda, ldb;
    if (MODE == 0) {
        Ahi = g_xh + (size_t)by * BM * ND; Alo = g_xl + (size_t)by * BM * ND;
        Bhi = g_Wh + (size_t)bx * BN * ND; Blo = g_Wl + (size_t)bx * BN * ND;
        lda = ND; ldb = ND;
    } else if (MODE == 1) {
        Ahi = g_hh + (size_t)by * BM * ND; Alo = g_hl + (size_t)by * BM * ND;
        Bhi = g_hh + (size_t)bx * BN * ND; Blo = g_hl + (size_t)bx * BN * ND;
        lda = ND; ldb = ND;
    } else {
        Ahi = g_Pf + (size_t)by * BM * NR; Alo = nullptr;
        Bhi = g_hT + (size_t)bx * BN * NR; Blo = nullptr;
        lda = NR; ldb = NR;
    }

    float c[2][8][4] = {};

    // prologue: stage 0
    {
        uint32_t st = sb;
        if (MODE < 2) {
            load_tile(Ahi, lda, 0, st + T_AHI, tid);
            load_tile(Alo, lda, 0, st + T_ALO, tid);
            load_tile(Bhi, ldb, 0, st + T_BHI, tid);
            load_tile(Blo, ldb, 0, st + T_BLO, tid);
        } else {
            load_tile(Ahi, lda, 0, st + 0, tid);
            load_tile(Bhi, ldb, 0, st + 8192, tid);
        }
        cp_commit();
    }

    for (int i = 0; i < NC; i++) {
        const int s = i & 1;
        if (i + 1 < NC) {
            uint32_t st = sb + (s ^ 1) * STAGE;
            int k0 = (i + 1) * BKD;
            if (MODE < 2) {
                load_tile(Ahi, lda, k0, st + T_AHI, tid);
                load_tile(Alo, lda, k0, st + T_ALO, tid);
                load_tile(Bhi, ldb, k0, st + T_BHI, tid);
                load_tile(Blo, ldb, k0, st + T_BLO, tid);
            } else {
                load_tile(Ahi, lda, k0, st + 0, tid);
                load_tile(Bhi, ldb, k0, st + 8192, tid);
            }
            cp_commit();
            cp_wait<1>();
        } else {
            cp_wait<0>();
        }
        __syncthreads();

        const uint32_t st = sb + s * STAGE;
        const int NP = (MODE < 2) ? 3 : 1;
        #pragma unroll
        for (int p = 0; p < NP; p++) {
            uint32_t aoff, boff;
            if (MODE < 2) {
                aoff = st + ((p == 1) ? T_ALO : T_AHI);
                boff = st + ((p == 2) ? T_BLO : T_BHI);
            } else { aoff = st; boff = st + 8192; }
            #pragma unroll
            for (int ks = 0; ks < 2; ks++) {
                uint32_t a[2][4];
                #pragma unroll
                for (int mf = 0; mf < 2; mf++) {
                    int row = mo + mf * 16 + (lane & 15);
                    int ch = 2 * ks + (lane >> 4);
                    ldsm4(a[mf], aoff + swz(row, ch));
                }
                uint32_t b[4][4];
                #pragma unroll
                for (int np = 0; np < 4; np++) {
                    int row = no + np * 16 + (lane & 7) + ((lane >> 4) << 3);
                    int ch = 2 * ks + ((lane >> 3) & 1);
                    ldsm4(b[np], boff + swz(row, ch));
                }
                #pragma unroll
                for (int mf = 0; mf < 2; mf++)
                    #pragma unroll
                    for (int nf = 0; nf < 8; nf++)
                        mma16816(c[mf][nf], a[mf],
                                 b[nf >> 1][(nf & 1) * 2], b[nf >> 1][(nf & 1) * 2 + 1]);
            }
        }
        __syncthreads();
    }

    // --------------------------------------------------------- epilogue
    __half* sp = (__half*)smem;            // [128][132] staging (aliases stages)
    const bool mirror = (MODE == 1) && (bx != by);
    float rs[2][2] = {};
    #pragma unroll
    for (int mf = 0; mf < 2; mf++) {
        const int rl0 = mo + mf * 16 + (lane >> 2);
        const int rl1 = rl0 + 8;
        const int r0 = by * BM + rl0, r1 = by * BM + rl1;
        float inv0 = 0.f, inv1 = 0.f;
        if (MODE == 2) {
            inv0 = 1.0f / __ldg(&g_rowsum[r0]);
            inv1 = 1.0f / __ldg(&g_rowsum[r1]);
        }
        #pragma unroll
        for (int nf = 0; nf < 8; nf++) {
            const int cl = no + nf * 8 + 2 * (lane & 3);
            const int col = bx * BN + cl;
            float v0 = c[mf][nf][0], v1 = c[mf][nf][1];
            float v2 = c[mf][nf][2], v3 = c[mf][nf][3];
            if (MODE == 0) {
                float b0 = __ldg(&bias[col]), b1 = __ldg(&bias[col + 1]);
                v0 += b0; v1 += b1; v2 += b0; v3 += b1;
                __half h0, l0, h1, l1, h2, l2, h3, l3;
                split16(v0, h0, l0); split16(v1, h1, l1);
                split16(v2, h2, l2); split16(v3, h3, l3);
                *(__half2*)(g_hh + (size_t)r0 * ND + col) = __halves2half2(h0, h1);
                *(__half2*)(g_hl + (size_t)r0 * ND + col) = __halves2half2(l0, l1);
                *(__half2*)(g_hh + (size_t)r1 * ND + col) = __halves2half2(h2, h3);
                *(__half2*)(g_hl + (size_t)r1 * ND + col) = __halves2half2(l2, l3);
            } else if (MODE == 1) {
                float p0 = __expf(ftanh(v0)), p1 = __expf(ftanh(v1));
                float p2 = __expf(ftanh(v2)), p3 = __expf(ftanh(v3));
                rs[mf][0] += p0 + p1; rs[mf][1] += p2 + p3;
                __half2 q0 = __halves2half2(__float2half_rn(p0), __float2half_rn(p1));
                __half2 q1 = __halves2half2(__float2half_rn(p2), __float2half_rn(p3));
                *(__half2*)(g_Pf + (size_t)r0 * NR + col) = q0;
                *(__half2*)(g_Pf + (size_t)r1 * NR + col) = q1;
                if (mirror) {
                    *(__half2*)(sp + rl0 * 132 + cl) = q0;
                    *(__half2*)(sp + rl1 * 132 + cl) = q1;
                }
            } else {
                float2 o0 = make_float2(tanhf(v0 * inv0), tanhf(v1 * inv0));
                float2 o1 = make_float2(tanhf(v2 * inv1), tanhf(v3 * inv1));
                *(float2*)(out + (size_t)r0 * ND + col) = o0;
                *(float2*)(out + (size_t)r1 * ND + col) = o1;
            }
        }
    }
    if (MODE == 1) {
        #pragma unroll
        for (int mf = 0; mf < 2; mf++)
            #pragma unroll
            for (int hh = 0; hh < 2; hh++) {
                float v = rs[mf][hh];
                v += __shfl_xor_sync(0xffffffffu, v, 1);
                v += __shfl_xor_sync(0xffffffffu, v, 2);
                if ((lane & 3) == 0) {
                    int r = by * BM + mo + mf * 16 + (lane >> 2) + hh * 8;
                    atomicAdd(&g_rowsum[r], v);
                }
            }
        if (mirror) {
            __syncthreads();
            // mirror block: write P[bx-range][by-range] coalesced + column sums
            const int cc = tid >> 1;            // local col 0..127
            const int rh = (tid & 1) * 64;      // row half
            float csum = 0.0f;
            #pragma unroll
            for (int q = 0; q < 8; q++) {
                __half tmp[8];
                #pragma unroll
                for (int r = 0; r < 8; r++) {
                    __half v = sp[(rh + q * 8 + r) * 132 + cc];
                    tmp[r] = v;
                    csum += __half2float(v);
                }
                *(uint4*)(g_Pf + (size_t)(bx * BN + cc) * NR + by * BM + rh + q * 8) =
                    *(uint4*)tmp;
            }
            float o = __shfl_down_sync(0xffffffffu, csum, 1);
            if ((lane & 1) == 0) atomicAdd(&g_rowsum[bx * BN + cc], csum + o);
        }
    }
}

// ------------------------------------------------------------- small kernels
__global__ void k_split(const float* __restrict__ src, __half* __restrict__ hi,
                        __half* __restrict__ lo, int n4)
{
    int i = blockIdx.x * blockDim.x + threadIdx.x;
    if (i >= n4) return;
    float4 v = ((const float4*)src)[i];
    __half h[4], l[4];
    split16(v.x, h[0], l[0]); split16(v.y, h[1], l[1]);
    split16(v.z, h[2], l[2]); split16(v.w, h[3], l[3]);
    ((uint2*)hi)[i] = *(uint2*)h;
    ((uint2*)lo)[i] = *(uint2*)l;
}
__global__ void k_zero_rowsum()
{
    int i = blockIdx.x * blockDim.x + threadIdx.x;
    if (i < NR) g_rowsum[i] = 0.0f;
}
// tiled transpose: g_hT[c][r] = g_hh[r][c]
__global__ void k_transpose()
{
    __shared__ __half t[32][33];
    int x = threadIdx.x, y = threadIdx.y;           // 32 x 8
    int r0 = blockIdx.y * 32, c0 = blockIdx.x * 32;
    #pragma unroll
    for (int i = 0; i < 32; i += 8)
        t[y + i][x] = g_hh[(size_t)(r0 + y + i) * ND + c0 + x];
    __syncthreads();
    #pragma unroll
    for (int i = 0; i < 32; i += 8)
        g_hT[(size_t)(c0 + y + i) * NR + r0 + x] = t[x][y + i];
}

// ------------------------------------------------------------------ launcher
extern "C" void kernel_launch(void* const* d_in, const int* in_sizes, int n_in,
                              void* d_out, int out_size)
{
    const float* x = (const float*)d_in[0];
    const float* W = (const float*)d_in[1];
    const float* b = (const float*)d_in[2];
    float* out = (float*)d_out;

    cudaFuncSetAttribute(gemm_tc<0>, cudaFuncAttributeMaxDynamicSharedMemorySize, 65536);
    cudaFuncSetAttribute(gemm_tc<1>, cudaFuncAttributeMaxDynamicSharedMemorySize, 65536);
    cudaFuncSetAttribute(gemm_tc<2>, cudaFuncAttributeMaxDynamicSharedMemorySize, 32768);

    __half *xh, *xl, *wh, *wl;
    cudaGetSymbolAddress((void**)&xh, g_xh); cudaGetSymbolAddress((void**)&xl, g_xl);
    cudaGetSymbolAddress((void**)&wh, g_Wh); cudaGetSymbolAddress((void**)&wl, g_Wl);

    int nx4 = NR * ND / 4, nw4 = ND * ND / 4;
    k_split<<<(nx4 + 255) / 256, 256>>>(x, xh, xl, nx4);
    k_split<<<(nw4 + 255) / 256, 256>>>(W, wh, wl, nw4);
    k_zero_rowsum<<<NR / 256, 256>>>();

    gemm_tc<0><<<dim3(ND / BN, NR / BM), NTHR, 65536>>>(b, nullptr);
    k_transpose<<<dim3(ND / 32, NR / 32), dim3(32, 8)>>>();
    gemm_tc<1><<<dim3(NR / BN, NR / BM), NTHR, 65536>>>(nullptr, nullptr);
    gemm_tc<2><<<dim3(ND / BN, NR / BM), NTHR, 32768>>>(nullptr, out);
}

// round 7
// speedup vs baseline: 8.8336x; 1.0212x over previous
#include <cuda_runtime.h>
#include <cuda_fp16.h>
#include <cstdint>
#include <math.h>

#define NR 8192
#define ND 1024
#define BM 128
#define BKD 32

// tile offsets within a stage (each [rows][32] fp16 tile: rows*64 bytes)
#define T_AHI 0
#define T_ALO 8192
#define T_BHI 16384
#define T_BLO 24576

// scratch
__device__ __half g_xh[(size_t)NR * ND], g_xl[(size_t)NR * ND];
__device__ __half g_Wh[(size_t)ND * ND], g_Wl[(size_t)ND * ND];
__device__ __half g_hh[(size_t)NR * ND], g_hl[(size_t)NR * ND];
__device__ __half g_hT[(size_t)ND * NR];
__device__ __half g_Pf[(size_t)NR * NR];
__device__ float g_rowsum[NR];

// ------------------------------------------------------------------ helpers
__device__ __forceinline__ uint32_t smem_u32(const void* p) {
    uint32_t a;
    asm("{ .reg .u64 t; cvta.to.shared.u64 t, %1; cvt.u32.u64 %0, t; }" : "=r"(a) : "l"(p));
    return a;
}
__device__ __forceinline__ void cp16(uint32_t s, const __half* g) {
    asm volatile("cp.async.cg.shared.global [%0], [%1], 16;"
                 :: "r"(s), "l"(__cvta_generic_to_global((const void*)g)) : "memory");
}
__device__ __forceinline__ void cp_commit() {
    asm volatile("cp.async.commit_group;" ::: "memory");
}
template <int N> __device__ __forceinline__ void cp_wait() {
    asm volatile("cp.async.wait_group %0;" :: "n"(N) : "memory");
}
__device__ __forceinline__ void ldsm4(uint32_t* r, uint32_t a) {
    asm volatile("ldmatrix.sync.aligned.m8n8.x4.shared.b16 {%0,%1,%2,%3}, [%4];"
                 : "=r"(r[0]), "=r"(r[1]), "=r"(r[2]), "=r"(r[3]) : "r"(a));
}
__device__ __forceinline__ void mma16816(float* c, const uint32_t* a, uint32_t b0, uint32_t b1) {
    asm volatile(
        "mma.sync.aligned.m16n8k16.row.col.f32.f16.f16.f32 "
        "{%0,%1,%2,%3},{%4,%5,%6,%7},{%8,%9},{%0,%1,%2,%3};"
        : "+f"(c[0]), "+f"(c[1]), "+f"(c[2]), "+f"(c[3])
        : "r"(a[0]), "r"(a[1]), "r"(a[2]), "r"(a[3]), "r"(b0), "r"(b1));
}
__device__ __forceinline__ float ftanh(float x) {
    float y; asm("tanh.approx.f32 %0, %1;" : "=f"(y) : "f"(x)); return y;
}
__device__ __forceinline__ void split16(float v, __half& h, __half& l) {
    h = __float2half_rn(v);
    l = __float2half_rn(v - __half2float(h));
}
// swizzled smem byte offset for (row, 16B-chunk) within a [rows][32] fp16 tile
__device__ __forceinline__ uint32_t swz(int row, int c) {
    return (uint32_t)(row * 64 + ((c ^ ((row >> 1) & 3)) << 4));
}

// load a [ITERS*THR/4 rows][32] fp16 tile
template <int THR, int ITERS>
__device__ __forceinline__ void load_tileT(const __half* __restrict__ base, size_t ld,
                                           int k0, uint32_t st, int tid) {
    #pragma unroll
    for (int i = 0; i < ITERS; i++) {
        int idx = tid + i * THR;
        int row = idx >> 2, c = idx & 3;
        cp16(st + swz(row, c), base + (size_t)row * ld + k0 + c * 8);
    }
}

// ------------------------------------------------------- GEMM (0=K1,1=K2,2=K3)
// MODE 1 computes only by<=bx blocks; mirrors P and accumulates row+col sums
// (tanh bounds scores, so exp needs no max subtraction).
// Pipeline: single-sync multistage. Per iter:
//   wait<S-2>; sync; issue loads for chunk i+S-1; commit; compute chunk i.
template <int MODE>
__global__ __launch_bounds__((MODE == 2) ? 512 : 256, (MODE == 2) ? 1 : 2)
void gemm_tc(const float* __restrict__ bias, float* __restrict__ out)
{
    constexpr int THR   = (MODE == 2) ? 512 : 256;
    constexpr int S     = (MODE == 2) ? 4 : 3;
    constexpr int STAGE = (MODE < 2) ? 32768 : 24576;   // both: 98304 total
    constexpr int BNx   = (MODE == 2) ? 256 : 128;
    constexpr int K     = (MODE == 2) ? NR : ND;
    constexpr int NC    = K / BKD;

    extern __shared__ char smem[];
    const uint32_t sb = smem_u32(smem);
    const int tid = threadIdx.x, lane = tid & 31, wid = tid >> 5;
    const int bx = blockIdx.x, by = blockIdx.y;
    if (MODE == 1 && by > bx) return;   // symmetry (uniform whole-CTA exit)
    const int mo = (wid & 3) * 32, no = (wid >> 2) * 64;

    const __half *Ahi, *Alo, *Bhi, *Blo;
    size_t lda, ldb;
    if (MODE == 0) {
        Ahi = g_xh + (size_t)by * BM * ND; Alo = g_xl + (size_t)by * BM * ND;
        Bhi = g_Wh + (size_t)bx * BNx * ND; Blo = g_Wl + (size_t)bx * BNx * ND;
        lda = ND; ldb = ND;
    } else if (MODE == 1) {
        Ahi = g_hh + (size_t)by * BM * ND; Alo = g_hl + (size_t)by * BM * ND;
        Bhi = g_hh + (size_t)bx * BNx * ND; Blo = g_hl + (size_t)bx * BNx * ND;
        lda = ND; ldb = ND;
    } else {
        Ahi = g_Pf + (size_t)by * BM * NR; Alo = nullptr;
        Bhi = g_hT + (size_t)bx * BNx * NR; Blo = nullptr;
        lda = NR; ldb = NR;
    }

    auto load_chunk = [&](int k0, uint32_t st) {
        if (MODE < 2) {
            load_tileT<THR, 2>(Ahi, lda, k0, st + T_AHI, tid);
            load_tileT<THR, 2>(Alo, lda, k0, st + T_ALO, tid);
            load_tileT<THR, 2>(Bhi, ldb, k0, st + T_BHI, tid);
            load_tileT<THR, 2>(Blo, ldb, k0, st + T_BLO, tid);
        } else {
            load_tileT<THR, 1>(Ahi, lda, k0, st + 0, tid);      // 128x32
            load_tileT<THR, 2>(Bhi, ldb, k0, st + 8192, tid);   // 256x32
        }
    };

    float c[2][8][4] = {};

    // prologue: chunks 0..S-2
    #pragma unroll
    for (int s = 0; s < S - 1; s++) {
        load_chunk(s * BKD, sb + s * STAGE);
        cp_commit();
    }

    for (int i = 0; i < NC; i++) {
        cp_wait<S - 2>();
        __syncthreads();

        if (i + S - 1 < NC)
            load_chunk((i + S - 1) * BKD, sb + ((i + S - 1) % S) * STAGE);
        cp_commit();

        const uint32_t st = sb + (i % S) * STAGE;
        const int NP = (MODE < 2) ? 3 : 1;
        #pragma unroll
        for (int p = 0; p < NP; p++) {
            uint32_t aoff, boff;
            if (MODE < 2) {
                aoff = st + ((p == 1) ? T_ALO : T_AHI);
                boff = st + ((p == 2) ? T_BLO : T_BHI);
            } else { aoff = st; boff = st + 8192; }
            #pragma unroll
            for (int ks = 0; ks < 2; ks++) {
                uint32_t a[2][4];
                #pragma unroll
                for (int mf = 0; mf < 2; mf++) {
                    int row = mo + mf * 16 + (lane & 15);
                    int ch = 2 * ks + (lane >> 4);
                    ldsm4(a[mf], aoff + swz(row, ch));
                }
                uint32_t b[4][4];
                #pragma unroll
                for (int np = 0; np < 4; np++) {
                    int row = no + np * 16 + (lane & 7) + ((lane >> 4) << 3);
                    int ch = 2 * ks + ((lane >> 3) & 1);
                    ldsm4(b[np], boff + swz(row, ch));
                }
                #pragma unroll
                for (int mf = 0; mf < 2; mf++)
                    #pragma unroll
                    for (int nf = 0; nf < 8; nf++)
                        mma16816(c[mf][nf], a[mf],
                                 b[nf >> 1][(nf & 1) * 2], b[nf >> 1][(nf & 1) * 2 + 1]);
            }
        }
    }
    __syncthreads();   // all compute smem reads done (epilogue aliases stages)

    // --------------------------------------------------------- epilogue
    __half* sp = (__half*)smem;            // [128][132] staging (aliases stages)
    const bool mirror = (MODE == 1) && (bx != by);
    float rs[2][2] = {};
    #pragma unroll
    for (int mf = 0; mf < 2; mf++) {
        const int rl0 = mo + mf * 16 + (lane >> 2);
        const int rl1 = rl0 + 8;
        const int r0 = by * BM + rl0, r1 = by * BM + rl1;
        float inv0 = 0.f, inv1 = 0.f;
        if (MODE == 2) {
            inv0 = 1.0f / __ldg(&g_rowsum[r0]);
            inv1 = 1.0f / __ldg(&g_rowsum[r1]);
        }
        #pragma unroll
        for (int nf = 0; nf < 8; nf++) {
            const int cl = no + nf * 8 + 2 * (lane & 3);
            const int col = bx * BNx + cl;
            float v0 = c[mf][nf][0], v1 = c[mf][nf][1];
            float v2 = c[mf][nf][2], v3 = c[mf][nf][3];
            if (MODE == 0) {
                float b0 = __ldg(&bias[col]), b1 = __ldg(&bias[col + 1]);
                v0 += b0; v1 += b1; v2 += b0; v3 += b1;
                __half h0, l0, h1, l1, h2, l2, h3, l3;
                split16(v0, h0, l0); split16(v1, h1, l1);
                split16(v2, h2, l2); split16(v3, h3, l3);
                *(__half2*)(g_hh + (size_t)r0 * ND + col) = __halves2half2(h0, h1);
                *(__half2*)(g_hl + (size_t)r0 * ND + col) = __halves2half2(l0, l1);
                *(__half2*)(g_hh + (size_t)r1 * ND + col) = __halves2half2(h2, h3);
                *(__half2*)(g_hl + (size_t)r1 * ND + col) = __halves2half2(l2, l3);
            } else if (MODE == 1) {
                float p0 = __expf(ftanh(v0)), p1 = __expf(ftanh(v1));
                float p2 = __expf(ftanh(v2)), p3 = __expf(ftanh(v3));
                rs[mf][0] += p0 + p1; rs[mf][1] += p2 + p3;
                __half2 q0 = __halves2half2(__float2half_rn(p0), __float2half_rn(p1));
                __half2 q1 = __halves2half2(__float2half_rn(p2), __float2half_rn(p3));
                *(__half2*)(g_Pf + (size_t)r0 * NR + col) = q0;
                *(__half2*)(g_Pf + (size_t)r1 * NR + col) = q1;
                if (mirror) {
                    *(__half2*)(sp + rl0 * 132 + cl) = q0;
                    *(__half2*)(sp + rl1 * 132 + cl) = q1;
                }
            } else {
                float2 o0 = make_float2(tanhf(v0 * inv0), tanhf(v1 * inv0));
                float2 o1 = make_float2(tanhf(v2 * inv1), tanhf(v3 * inv1));
                *(float2*)(out + (size_t)r0 * ND + col) = o0;
                *(float2*)(out + (size_t)r1 * ND + col) = o1;
            }
        }
    }
    if (MODE == 1) {
        #pragma unroll
        for (int mf = 0; mf < 2; mf++)
            #pragma unroll
            for (int hh = 0; hh < 2; hh++) {
                float v = rs[mf][hh];
                v += __shfl_xor_sync(0xffffffffu, v, 1);
                v += __shfl_xor_sync(0xffffffffu, v, 2);
                if ((lane & 3) == 0) {
                    int r = by * BM + mo + mf * 16 + (lane >> 2) + hh * 8;
                    atomicAdd(&g_rowsum[r], v);
                }
            }
        if (mirror) {
            __syncthreads();
            // mirror block: write P[bx-range][by-range] coalesced + column sums
            const int cc = tid >> 1;            // local col 0..127
            const int rh = (tid & 1) * 64;      // row half
            float csum = 0.0f;
            #pragma unroll
            for (int q = 0; q < 8; q++) {
                __half tmp[8];
                #pragma unroll
                for (int r = 0; r < 8; r++) {
                    __half v = sp[(rh + q * 8 + r) * 132 + cc];
                    tmp[r] = v;
                    csum += __half2float(v);
                }
                *(uint4*)(g_Pf + (size_t)(bx * BNx + cc) * NR + by * BM + rh + q * 8) =
                    *(uint4*)tmp;
            }
            float o = __shfl_down_sync(0xffffffffu, csum, 1);
            if ((lane & 1) == 0) atomicAdd(&g_rowsum[bx * BNx + cc], csum + o);
        }
    }
}

// ------------------------------------------------------------- small kernels
__global__ void k_split(const float* __restrict__ src, __half* __restrict__ hi,
                        __half* __restrict__ lo, int n4)
{
    int i = blockIdx.x * blockDim.x + threadIdx.x;
    if (i >= n4) return;
    float4 v = ((const float4*)src)[i];
    __half h[4], l[4];
    split16(v.x, h[0], l[0]); split16(v.y, h[1], l[1]);
    split16(v.z, h[2], l[2]); split16(v.w, h[3], l[3]);
    ((uint2*)hi)[i] = *(uint2*)h;
    ((uint2*)lo)[i] = *(uint2*)l;
}
__global__ void k_zero_rowsum()
{
    int i = blockIdx.x * blockDim.x + threadIdx.x;
    if (i < NR) g_rowsum[i] = 0.0f;
}
// tiled transpose: g_hT[c][r] = g_hh[r][c]
__global__ void k_transpose()
{
    __shared__ __half t[32][33];
    int x = threadIdx.x, y = threadIdx.y;           // 32 x 8
    int r0 = blockIdx.y * 32, c0 = blockIdx.x * 32;
    #pragma unroll
    for (int i = 0; i < 32; i += 8)
        t[y + i][x] = g_hh[(size_t)(r0 + y + i) * ND + c0 + x];
    __syncthreads();
    #pragma unroll
    for (int i = 0; i < 32; i += 8)
        g_hT[(size_t)(c0 + y + i) * NR + r0 + x] = t[x][y + i];
}

// ------------------------------------------------------------------ launcher
extern "C" void kernel_launch(void* const* d_in, const int* in_sizes, int n_in,
                              void* d_out, int out_size)
{
    const float* x = (const float*)d_in[0];
    const float* W = (const float*)d_in[1];
    const float* b = (const float*)d_in[2];
    float* out = (float*)d_out;

    cudaFuncSetAttribute(gemm_tc<0>, cudaFuncAttributeMaxDynamicSharedMemorySize, 98304);
    cudaFuncSetAttribute(gemm_tc<1>, cudaFuncAttributeMaxDynamicSharedMemorySize, 98304);
    cudaFuncSetAttribute(gemm_tc<2>, cudaFuncAttributeMaxDynamicSharedMemorySize, 98304);

    __half *xh, *xl, *wh, *wl;
    cudaGetSymbolAddress((void**)&xh, g_xh); cudaGetSymbolAddress((void**)&xl, g_xl);
    cudaGetSymbolAddress((void**)&wh, g_Wh); cudaGetSymbolAddress((void**)&wl, g_Wl);

    int nx4 = NR * ND / 4, nw4 = ND * ND / 4;
    k_split<<<(nx4 + 255) / 256, 256>>>(x, xh, xl, nx4);
    k_split<<<(nw4 + 255) / 256, 256>>>(W, wh, wl, nw4);
    k_zero_rowsum<<<NR / 256, 256>>>();

    gemm_tc<0><<<dim3(ND / 128, NR / BM), 256, 98304>>>(b, nullptr);
    k_transpose<<<dim3(ND / 32, NR / 32), dim3(32, 8)>>>();
    gemm_tc<1><<<dim3(NR / 128, NR / BM), 256, 98304>>>(nullptr, nullptr);
    gemm_tc<2><<<dim3(ND / 256, NR / BM), 512, 98304>>>(nullptr, out);
}

// round 8
// speedup vs baseline: 8.8339x; 1.0000x over previous
#include <cuda_runtime.h>
#include <cuda_fp16.h>
#include <cstdint>
#include <math.h>

#define NR 8192
#define ND 1024
#define BM 128
#define BKD 32

// tile offsets within a stage (each [rows][32] fp16 tile: rows*64 bytes)
#define T_AHI 0
#define T_ALO 8192
#define T_BHI 16384
#define T_BLO 24576

// scratch
__device__ __half g_xh[(size_t)NR * ND], g_xl[(size_t)NR * ND];
__device__ __half g_Wh[(size_t)ND * ND], g_Wl[(size_t)ND * ND];
__device__ __half g_hh[(size_t)NR * ND], g_hl[(size_t)NR * ND];
__device__ __half g_hT[(size_t)ND * NR];
__device__ __half g_Pf[(size_t)NR * NR];
__device__ float g_rowsum[NR];

// ------------------------------------------------------------------ helpers
__device__ __forceinline__ uint32_t smem_u32(const void* p) {
    uint32_t a;
    asm("{ .reg .u64 t; cvta.to.shared.u64 t, %1; cvt.u32.u64 %0, t; }" : "=r"(a) : "l"(p));
    return a;
}
__device__ __forceinline__ void cp16(uint32_t s, const __half* g) {
    asm volatile("cp.async.cg.shared.global [%0], [%1], 16;"
                 :: "r"(s), "l"(__cvta_generic_to_global((const void*)g)) : "memory");
}
__device__ __forceinline__ void cp_commit() {
    asm volatile("cp.async.commit_group;" ::: "memory");
}
template <int N> __device__ __forceinline__ void cp_wait() {
    asm volatile("cp.async.wait_group %0;" :: "n"(N) : "memory");
}
__device__ __forceinline__ void ldsm4(uint32_t* r, uint32_t a) {
    asm volatile("ldmatrix.sync.aligned.m8n8.x4.shared.b16 {%0,%1,%2,%3}, [%4];"
                 : "=r"(r[0]), "=r"(r[1]), "=r"(r[2]), "=r"(r[3]) : "r"(a));
}
__device__ __forceinline__ void mma16816(float* c, const uint32_t* a, uint32_t b0, uint32_t b1) {
    asm volatile(
        "mma.sync.aligned.m16n8k16.row.col.f32.f16.f16.f32 "
        "{%0,%1,%2,%3},{%4,%5,%6,%7},{%8,%9},{%0,%1,%2,%3};"
        : "+f"(c[0]), "+f"(c[1]), "+f"(c[2]), "+f"(c[3])
        : "r"(a[0]), "r"(a[1]), "r"(a[2]), "r"(a[3]), "r"(b0), "r"(b1));
}
__device__ __forceinline__ float ftanh(float x) {
    float y; asm("tanh.approx.f32 %0, %1;" : "=f"(y) : "f"(x)); return y;
}
__device__ __forceinline__ void split16(float v, __half& h, __half& l) {
    h = __float2half_rn(v);
    l = __float2half_rn(v - __half2float(h));
}
// swizzled smem byte offset for (row, 16B-chunk) within a [rows][32] fp16 tile
__device__ __forceinline__ uint32_t swz(int row, int c) {
    return (uint32_t)(row * 64 + ((c ^ ((row >> 1) & 3)) << 4));
}

// load a [ITERS*THR/4 rows][32] fp16 tile
template <int THR, int ITERS>
__device__ __forceinline__ void load_tileT(const __half* __restrict__ base, size_t ld,
                                           int k0, uint32_t st, int tid) {
    #pragma unroll
    for (int i = 0; i < ITERS; i++) {
        int idx = tid + i * THR;
        int row = idx >> 2, c = idx & 3;
        cp16(st + swz(row, c), base + (size_t)row * ld + k0 + c * 8);
    }
}

// ------------------------------------------------------- GEMM (0=K1,1=K2,2=K3)
// MODE 1 computes only by<=bx blocks; mirrors P and accumulates row+col sums
// (tanh bounds scores, so exp needs no max subtraction).
// Inner loop reuses fragments across the 3 limb products:
//   load ahi,bhi -> ahi*bhi; load blo -> ahi*blo; load alo -> alo*bhi
// (12 LDSM.x4 per ks-pair instead of 18 -> smem crossbar relief).
template <int MODE>
__global__ __launch_bounds__((MODE == 2) ? 512 : 256, (MODE == 2) ? 1 : 2)
void gemm_tc(const float* __restrict__ bias, float* __restrict__ out)
{
    constexpr int THR   = (MODE == 2) ? 512 : 256;
    constexpr int S     = (MODE == 2) ? 4 : 3;
    constexpr int STAGE = (MODE < 2) ? 32768 : 24576;   // both: 98304 total
    constexpr int BNx   = (MODE == 2) ? 256 : 128;
    constexpr int K     = (MODE == 2) ? NR : ND;
    constexpr int NC    = K / BKD;

    extern __shared__ char smem[];
    const uint32_t sb = smem_u32(smem);
    const int tid = threadIdx.x, lane = tid & 31, wid = tid >> 5;
    const int bx = blockIdx.x, by = blockIdx.y;
    if (MODE == 1 && by > bx) return;   // symmetry (uniform whole-CTA exit)
    const int mo = (wid & 3) * 32, no = (wid >> 2) * 64;

    const __half *Ahi, *Alo, *Bhi, *Blo;
    size_t lda, ldb;
    if (MODE == 0) {
        Ahi = g_xh + (size_t)by * BM * ND; Alo = g_xl + (size_t)by * BM * ND;
        Bhi = g_Wh + (size_t)bx * BNx * ND; Blo = g_Wl + (size_t)bx * BNx * ND;
        lda = ND; ldb = ND;
    } else if (MODE == 1) {
        Ahi = g_hh + (size_t)by * BM * ND; Alo = g_hl + (size_t)by * BM * ND;
        Bhi = g_hh + (size_t)bx * BNx * ND; Blo = g_hl + (size_t)bx * BNx * ND;
        lda = ND; ldb = ND;
    } else {
        Ahi = g_Pf + (size_t)by * BM * NR; Alo = nullptr;
        Bhi = g_hT + (size_t)bx * BNx * NR; Blo = nullptr;
        lda = NR; ldb = NR;
    }

    auto load_chunk = [&](int k0, uint32_t st) {
        if (MODE < 2) {
            load_tileT<THR, 2>(Ahi, lda, k0, st + T_AHI, tid);
            load_tileT<THR, 2>(Alo, lda, k0, st + T_ALO, tid);
            load_tileT<THR, 2>(Bhi, ldb, k0, st + T_BHI, tid);
            load_tileT<THR, 2>(Blo, ldb, k0, st + T_BLO, tid);
        } else {
            load_tileT<THR, 1>(Ahi, lda, k0, st + 0, tid);      // 128x32
            load_tileT<THR, 2>(Bhi, ldb, k0, st + 8192, tid);   // 256x32
        }
    };

    float c[2][8][4] = {};

    // prologue: chunks 0..S-2
    #pragma unroll
    for (int s = 0; s < S - 1; s++) {
        load_chunk(s * BKD, sb + s * STAGE);
        cp_commit();
    }

    for (int i = 0; i < NC; i++) {
        cp_wait<S - 2>();
        __syncthreads();

        if (i + S - 1 < NC)
            load_chunk((i + S - 1) * BKD, sb + ((i + S - 1) % S) * STAGE);
        cp_commit();

        const uint32_t st = sb + (i % S) * STAGE;
        #pragma unroll
        for (int ks = 0; ks < 2; ks++) {
            if (MODE < 2) {
                uint32_t ahi[2][4], bhi[4][4], tmp[4][4];
                // A-hi fragments
                #pragma unroll
                for (int mf = 0; mf < 2; mf++) {
                    int row = mo + mf * 16 + (lane & 15);
                    int ch = 2 * ks + (lane >> 4);
                    ldsm4(ahi[mf], st + T_AHI + swz(row, ch));
                }
                // B-hi fragments
                #pragma unroll
                for (int np = 0; np < 4; np++) {
                    int row = no + np * 16 + (lane & 7) + ((lane >> 4) << 3);
                    int ch = 2 * ks + ((lane >> 3) & 1);
                    ldsm4(bhi[np], st + T_BHI + swz(row, ch));
                }
                // product 1: ahi * bhi
                #pragma unroll
                for (int mf = 0; mf < 2; mf++)
                    #pragma unroll
                    for (int nf = 0; nf < 8; nf++)
                        mma16816(c[mf][nf], ahi[mf],
                                 bhi[nf >> 1][(nf & 1) * 2], bhi[nf >> 1][(nf & 1) * 2 + 1]);
                // product 2: ahi * blo (tmp holds blo)
                #pragma unroll
                for (int np = 0; np < 4; np++) {
                    int row = no + np * 16 + (lane & 7) + ((lane >> 4) << 3);
                    int ch = 2 * ks + ((lane >> 3) & 1);
                    ldsm4(tmp[np], st + T_BLO + swz(row, ch));
                }
                #pragma unroll
                for (int mf = 0; mf < 2; mf++)
                    #pragma unroll
                    for (int nf = 0; nf < 8; nf++)
                        mma16816(c[mf][nf], ahi[mf],
                                 tmp[nf >> 1][(nf & 1) * 2], tmp[nf >> 1][(nf & 1) * 2 + 1]);
                // product 3: alo * bhi (tmp[0..1] holds alo)
                #pragma unroll
                for (int mf = 0; mf < 2; mf++) {
                    int row = mo + mf * 16 + (lane & 15);
                    int ch = 2 * ks + (lane >> 4);
                    ldsm4(tmp[mf], st + T_ALO + swz(row, ch));
                }
                #pragma unroll
                for (int mf = 0; mf < 2; mf++)
                    #pragma unroll
                    for (int nf = 0; nf < 8; nf++)
                        mma16816(c[mf][nf], tmp[mf],
                                 bhi[nf >> 1][(nf & 1) * 2], bhi[nf >> 1][(nf & 1) * 2 + 1]);
            } else {
                uint32_t a[2][4], b[4][4];
                #pragma unroll
                for (int mf = 0; mf < 2; mf++) {
                    int row = mo + mf * 16 + (lane & 15);
                    int ch = 2 * ks + (lane >> 4);
                    ldsm4(a[mf], st + swz(row, ch));
                }
                #pragma unroll
                for (int np = 0; np < 4; np++) {
                    int row = no + np * 16 + (lane & 7) + ((lane >> 4) << 3);
                    int ch = 2 * ks + ((lane >> 3) & 1);
                    ldsm4(b[np], st + 8192 + swz(row, ch));
                }
                #pragma unroll
                for (int mf = 0; mf < 2; mf++)
                    #pragma unroll
                    for (int nf = 0; nf < 8; nf++)
                        mma16816(c[mf][nf], a[mf],
                                 b[nf >> 1][(nf & 1) * 2], b[nf >> 1][(nf & 1) * 2 + 1]);
            }
        }
    }
    __syncthreads();   // all compute smem reads done (epilogue aliases stages)

    // --------------------------------------------------------- epilogue
    __half* sp = (__half*)smem;            // [128][132] staging (aliases stages)
    const bool mirror = (MODE == 1) && (bx != by);
    float rs[2][2] = {};
    #pragma unroll
    for (int mf = 0; mf < 2; mf++) {
        const int rl0 = mo + mf * 16 + (lane >> 2);
        const int rl1 = rl0 + 8;
        const int r0 = by * BM + rl0, r1 = by * BM + rl1;
        float inv0 = 0.f, inv1 = 0.f;
        if (MODE == 2) {
            inv0 = 1.0f / __ldg(&g_rowsum[r0]);
            inv1 = 1.0f / __ldg(&g_rowsum[r1]);
        }
        #pragma unroll
        for (int nf = 0; nf < 8; nf++) {
            const int cl = no + nf * 8 + 2 * (lane & 3);
            const int col = bx * BNx + cl;
            float v0 = c[mf][nf][0], v1 = c[mf][nf][1];
            float v2 = c[mf][nf][2], v3 = c[mf][nf][3];
            if (MODE == 0) {
                float b0 = __ldg(&bias[col]), b1 = __ldg(&bias[col + 1]);
                v0 += b0; v1 += b1; v2 += b0; v3 += b1;
                __half h0, l0, h1, l1, h2, l2, h3, l3;
                split16(v0, h0, l0); split16(v1, h1, l1);
                split16(v2, h2, l2); split16(v3, h3, l3);
                *(__half2*)(g_hh + (size_t)r0 * ND + col) = __halves2half2(h0, h1);
                *(__half2*)(g_hl + (size_t)r0 * ND + col) = __halves2half2(l0, l1);
                *(__half2*)(g_hh + (size_t)r1 * ND + col) = __halves2half2(h2, h3);
                *(__half2*)(g_hl + (size_t)r1 * ND + col) = __halves2half2(l2, l3);
            } else if (MODE == 1) {
                float p0 = __expf(ftanh(v0)), p1 = __expf(ftanh(v1));
                float p2 = __expf(ftanh(v2)), p3 = __expf(ftanh(v3));
                rs[mf][0] += p0 + p1; rs[mf][1] += p2 + p3;
                __half2 q0 = __halves2half2(__float2half_rn(p0), __float2half_rn(p1));
                __half2 q1 = __halves2half2(__float2half_rn(p2), __float2half_rn(p3));
                *(__half2*)(g_Pf + (size_t)r0 * NR + col) = q0;
                *(__half2*)(g_Pf + (size_t)r1 * NR + col) = q1;
                if (mirror) {
                    *(__half2*)(sp + rl0 * 132 + cl) = q0;
                    *(__half2*)(sp + rl1 * 132 + cl) = q1;
                }
            } else {
                float2 o0 = make_float2(tanhf(v0 * inv0), tanhf(v1 * inv0));
                float2 o1 = make_float2(tanhf(v2 * inv1), tanhf(v3 * inv1));
                *(float2*)(out + (size_t)r0 * ND + col) = o0;
                *(float2*)(out + (size_t)r1 * ND + col) = o1;
            }
        }
    }
    if (MODE == 1) {
        #pragma unroll
        for (int mf = 0; mf < 2; mf++)
            #pragma unroll
            for (int hh = 0; hh < 2; hh++) {
                float v = rs[mf][hh];
                v += __shfl_xor_sync(0xffffffffu, v, 1);
                v += __shfl_xor_sync(0xffffffffu, v, 2);
                if ((lane & 3) == 0) {
                    int r = by * BM + mo + mf * 16 + (lane >> 2) + hh * 8;
                    atomicAdd(&g_rowsum[r], v);
                }
            }
        if (mirror) {
            __syncthreads();
            // mirror block: write P[bx-range][by-range] coalesced + column sums
            const int cc = tid >> 1;            // local col 0..127
            const int rh = (tid & 1) * 64;      // row half
            float csum = 0.0f;
            #pragma unroll
            for (int q = 0; q < 8; q++) {
                __half tmp[8];
                #pragma unroll
                for (int r = 0; r < 8; r++) {
                    __half v = sp[(rh + q * 8 + r) * 132 + cc];
                    tmp[r] = v;
                    csum += __half2float(v);
                }
                *(uint4*)(g_Pf + (size_t)(bx * BNx + cc) * NR + by * BM + rh + q * 8) =
                    *(uint4*)tmp;
            }
            float o = __shfl_down_sync(0xffffffffu, csum, 1);
            if ((lane & 1) == 0) atomicAdd(&g_rowsum[bx * BNx + cc], csum + o);
        }
    }
}

// ------------------------------------------------------------- small kernels
__global__ void k_split(const float* __restrict__ src, __half* __restrict__ hi,
                        __half* __restrict__ lo, int n4)
{
    int i = blockIdx.x * blockDim.x + threadIdx.x;
    if (i >= n4) return;
    float4 v = ((const float4*)src)[i];
    __half h[4], l[4];
    split16(v.x, h[0], l[0]); split16(v.y, h[1], l[1]);
    split16(v.z, h[2], l[2]); split16(v.w, h[3], l[3]);
    ((uint2*)hi)[i] = *(uint2*)h;
    ((uint2*)lo)[i] = *(uint2*)l;
}
__global__ void k_zero_rowsum()
{
    int i = blockIdx.x * blockDim.x + threadIdx.x;
    if (i < NR) g_rowsum[i] = 0.0f;
}
// tiled transpose: g_hT[c][r] = g_hh[r][c]
__global__ void k_transpose()
{
    __shared__ __half t[32][33];
    int x = threadIdx.x, y = threadIdx.y;           // 32 x 8
    int r0 = blockIdx.y * 32, c0 = blockIdx.x * 32;
    #pragma unroll
    for (int i = 0; i < 32; i += 8)
        t[y + i][x] = g_hh[(size_t)(r0 + y + i) * ND + c0 + x];
    __syncthreads();
    #pragma unroll
    for (int i = 0; i < 32; i += 8)
        g_hT[(size_t)(c0 + y + i) * NR + r0 + x] = t[x][y + i];
}

// ------------------------------------------------------------------ launcher
extern "C" void kernel_launch(void* const* d_in, const int* in_sizes, int n_in,
                              void* d_out, int out_size)
{
    const float* x = (const float*)d_in[0];
    const float* W = (const float*)d_in[1];
    const float* b = (const float*)d_in[2];
    float* out = (float*)d_out;

    cudaFuncSetAttribute(gemm_tc<0>, cudaFuncAttributeMaxDynamicSharedMemorySize, 98304);
    cudaFuncSetAttribute(gemm_tc<1>, cudaFuncAttributeMaxDynamicSharedMemorySize, 98304);
    cudaFuncSetAttribute(gemm_tc<2>, cudaFuncAttributeMaxDynamicSharedMemorySize, 98304);

    __half *xh, *xl, *wh, *wl;
    cudaGetSymbolAddress((void**)&xh, g_xh); cudaGetSymbolAddress((void**)&xl, g_xl);
    cudaGetSymbolAddress((void**)&wh, g_Wh); cudaGetSymbolAddress((void**)&wl, g_Wl);

    int nx4 = NR * ND / 4, nw4 = ND * ND / 4;
    k_split<<<(nx4 + 255) / 256, 256>>>(x, xh, xl, nx4);
    k_split<<<(nw4 + 255) / 256, 256>>>(W, wh, wl, nw4);
    k_zero_rowsum<<<NR / 256, 256>>>();

    gemm_tc<0><<<dim3(ND / 128, NR / BM), 256, 98304>>>(b, nullptr);
    k_transpose<<<dim3(ND / 32, NR / 32), dim3(32, 8)>>>();
    gemm_tc<1><<<dim3(NR / 128, NR / BM), 256, 98304>>>(nullptr, nullptr);
    gemm_tc<2><<<dim3(ND / 256, NR / BM), 512, 98304>>>(nullptr, out);
}